// round 4
// baseline (speedup 1.0000x reference)
#include <cuda_runtime.h>
#include <cuda_bf16.h>
#include <cstdint>

// ---------------- problem constants ----------------
#define B_    16
#define CIN   512
#define COUT  256
#define H_    56
#define W_    56
#define HO    28
#define WO    28
#define NPB   784
#define NTOT  (B_ * NPB)      // 12544
#define HW    (H_ * W_)       // 3136
#define CH    32              // channels per k-chunk
#define NCHK  (CIN / CH)      // 16 chunks
#define BN    64              // n per CTA
#define BM    256             // full M per CTA

// smem layout (bytes)
#define A_OFF 0               // 2 x 32KB  A tiles [m][hi64B|lo64B] 128B rows
#define X_OFF 65536           // 2 x 32KB  raw x   [c][r][pair] 16B units
#define BT_OFF 131072         // 8KB: B hi (32x128B) then B lo (+4096)
#define S_OFF 139264          // s_sc[512], s_sh[512]
#define SMEM_TOT 143360

__device__ __forceinline__ uint32_t smem_u32(const void* p) {
    uint32_t a;
    asm("{ .reg .u64 t; cvta.to.shared.u64 t, %1; cvt.u32.u64 %0, t; }" : "=r"(a) : "l"(p));
    return a;
}
#define CP_ASYNC16(dst_u32, src_ptr) \
    asm volatile("cp.async.cg.shared.global [%0], [%1], 16;" :: "r"(dst_u32), "l"(src_ptr))
#define CP_COMMIT() asm volatile("cp.async.commit_group;")
#define CP_WAIT1()  asm volatile("cp.async.wait_group 1;")

#define LDSM4(R0, R1, R2, R3, A) \
    asm volatile("ldmatrix.sync.aligned.m8n8.x4.shared.b16 {%0,%1,%2,%3}, [%4];" \
                 : "=r"(R0), "=r"(R1), "=r"(R2), "=r"(R3) : "r"(A))
#define LDSM4T(R0, R1, R2, R3, A) \
    asm volatile("ldmatrix.sync.aligned.m8n8.x4.trans.shared.b16 {%0,%1,%2,%3}, [%4];" \
                 : "=r"(R0), "=r"(R1), "=r"(R2), "=r"(R3) : "r"(A))

#define MMA16816(C, A0, A1, A2, A3, B0, B1) \
    asm volatile("mma.sync.aligned.m16n8k16.row.col.f32.bf16.bf16.f32 " \
                 "{%0,%1,%2,%3}, {%4,%5,%6,%7}, {%8,%9}, {%0,%1,%2,%3};" \
                 : "+f"((C)[0]), "+f"((C)[1]), "+f"((C)[2]), "+f"((C)[3]) \
                 : "r"(A0), "r"(A1), "r"(A2), "r"(A3), "r"(B0), "r"(B1))

// ============================================================================
// Single fused kernel: BN+ReLU+pool + W split + bf16x3 tensor-core GEMM
// ============================================================================
__global__ __launch_bounds__(256, 1)
void fused_all(const float* __restrict__ x,
               const float* __restrict__ gamma,
               const float* __restrict__ beta,
               const float* __restrict__ mean,
               const float* __restrict__ var,
               const float* __restrict__ Wc,
               float* __restrict__ out) {
    extern __shared__ char sm[];
    const uint32_t sb = smem_u32(sm);
    const int tid = threadIdx.x;
    const int lid = tid & 31, wid = tid >> 5;
    const int n0 = blockIdx.x * BN;

    float* s_sc = (float*)(sm + S_OFF);
    float* s_sh = (float*)(sm + S_OFF + 2048);

    // ---- prolog: BN constants into smem ----
    {
        int c = tid;
        float sc = gamma[c] * rsqrtf(var[c] + 1e-5f);
        s_sc[c] = sc;  s_sh[c] = beta[c] - mean[c] * sc;
        c += 256;
        sc = gamma[c] * rsqrtf(var[c] + 1e-5f);
        s_sc[c] = sc;  s_sh[c] = beta[c] - mean[c] * sc;
    }

    // ---- producer precompute: x-copy role (pair of adjacent n) ----
    const int pr = tid & 31;            // pair index 0..31  (n = n0 + 2*pr, +1)
    const int cg = tid >> 5;            // c-group 0..7
    const int nn = n0 + 2 * pr;
    const int bb = nn / NPB;
    const int pp = nn - bb * NPB;
    const int ho = pp / WO, wo = pp - ho * WO;   // wo even
    const float* xpair = x + ((size_t)bb * CIN * H_ + 2 * ho) * W_ + 2 * wo;

    // ---- W-split role ----
    const int ufp = tid & 7;            // float4 unit within 32-ch row
    const int mr0 = tid >> 3;           // m row 0..31 (+32g)
    const float* wrow = Wc + (size_t)mr0 * CIN + ufp * 4;

    // ---- consumer role: warp tile 64m x 32n ----
    const int wm = wid & 3, wn = wid >> 2;
    const int half = lid >> 4;

    float acc[4][4][4];
#pragma unroll
    for (int a = 0; a < 4; a++)
#pragma unroll
        for (int b = 0; b < 4; b++)
#pragma unroll
            for (int c = 0; c < 4; c++) acc[a][b][c] = 0.f;

    // ---- x tile async copy (chunk j -> buffer j&1) ----
    auto copy_x = [&](int j) {
        const float* xc = xpair + (size_t)j * CH * HW;
        uint32_t dst = sb + X_OFF + (uint32_t)(j & 1) * 32768 + pr * 16;
#pragma unroll
        for (int i2 = 0; i2 < 4; i2++) {
            int cl = cg + 8 * i2;
            const float* s0 = xc + (size_t)cl * HW;
            CP_ASYNC16(dst + cl * 1024,       s0);
            CP_ASYNC16(dst + cl * 1024 + 512, s0 + W_);
        }
    };

    // ---- W chunk -> A tile (buffer j&1), fp32->bf16 hi/lo split ----
    auto w_split = [&](int j) {
        const float* ws = wrow + j * CH;
        char* abase = sm + A_OFF + (size_t)(j & 1) * 32768;
#pragma unroll
        for (int g = 0; g < 8; g++) {
            float4 wv = *(const float4*)(ws + (size_t)g * 32 * CIN);
            int m = mr0 + 32 * g;
            __nv_bfloat16 h0 = __float2bfloat16(wv.x), h1 = __float2bfloat16(wv.y);
            __nv_bfloat16 h2 = __float2bfloat16(wv.z), h3 = __float2bfloat16(wv.w);
            __nv_bfloat16 l0 = __float2bfloat16(wv.x - __bfloat162float(h0));
            __nv_bfloat16 l1 = __float2bfloat16(wv.y - __bfloat162float(h1));
            __nv_bfloat16 l2 = __float2bfloat16(wv.z - __bfloat162float(h2));
            __nv_bfloat16 l3 = __float2bfloat16(wv.w - __bfloat162float(h3));
            uint2 hp, lp;
            hp.x = ((uint32_t)__bfloat16_as_ushort(h1) << 16) | __bfloat16_as_ushort(h0);
            hp.y = ((uint32_t)__bfloat16_as_ushort(h3) << 16) | __bfloat16_as_ushort(h2);
            lp.x = ((uint32_t)__bfloat16_as_ushort(l1) << 16) | __bfloat16_as_ushort(l0);
            lp.y = ((uint32_t)__bfloat16_as_ushort(l3) << 16) | __bfloat16_as_ushort(l2);
            uint32_t rowb = (uint32_t)m * 128 + (ufp & 1) * 8;
            *(uint2*)(abase + rowb + ((uint32_t)((ufp >> 1) ^ (m & 7)) * 16))       = hp;
            *(uint2*)(abase + rowb + ((uint32_t)(((ufp >> 1) | 4) ^ (m & 7)) * 16)) = lp;
        }
    };

    // ---- prologue ----
    copy_x(0); CP_COMMIT();
    w_split(0);

    for (int i = 0; i < NCHK; i++) {
        if (i + 1 < NCHK) copy_x(i + 1);
        CP_COMMIT();
        CP_WAIT1();            // chunk i raw-x resident
        __syncthreads();       // x(i), A(i) visible; B(i-1) fully consumed

        // ---- pool phase: xraw(i) -> B tile (k-major, SW128) ----
        {
            const char* xbase = sm + X_OFF + (size_t)(i & 1) * 32768 + pr * 16;
            const int ch0 = i * CH;
#pragma unroll
            for (int i2 = 0; i2 < 4; i2++) {
                int cl = cg + 8 * i2;
                float sc = s_sc[ch0 + cl], sh = s_sh[ch0 + cl];
                float4 r0 = *(const float4*)(xbase + cl * 1024);
                float4 r1 = *(const float4*)(xbase + cl * 1024 + 512);
                float v0 = fmaxf(fmaf(r0.x, sc, sh), 0.f) + fmaxf(fmaf(r0.y, sc, sh), 0.f)
                         + fmaxf(fmaf(r1.x, sc, sh), 0.f) + fmaxf(fmaf(r1.y, sc, sh), 0.f);
                float v1 = fmaxf(fmaf(r0.z, sc, sh), 0.f) + fmaxf(fmaf(r0.w, sc, sh), 0.f)
                         + fmaxf(fmaf(r1.z, sc, sh), 0.f) + fmaxf(fmaf(r1.w, sc, sh), 0.f);
                v0 *= 0.25f; v1 *= 0.25f;
                __nv_bfloat16 h0 = __float2bfloat16(v0), h1 = __float2bfloat16(v1);
                __nv_bfloat16 e0 = __float2bfloat16(v0 - __bfloat162float(h0));
                __nv_bfloat16 e1 = __float2bfloat16(v1 - __bfloat162float(h1));
                uint32_t hp = ((uint32_t)__bfloat16_as_ushort(h1) << 16) | __bfloat16_as_ushort(h0);
                uint32_t lp = ((uint32_t)__bfloat16_as_ushort(e1) << 16) | __bfloat16_as_ushort(e0);
                // row k = cl; n-pair byte: unit = pr>>2, sub = (pr&3)*4
                uint32_t ba = (uint32_t)cl * 128
                            + ((uint32_t)((pr >> 2) ^ (cl & 7)) * 16) + (pr & 3) * 4;
                *(uint32_t*)(sm + BT_OFF + ba)        = hp;
                *(uint32_t*)(sm + BT_OFF + 4096 + ba) = lp;
            }
        }

        if (i + 1 < NCHK) w_split(i + 1);   // fills A[(i+1)&1]
        __syncthreads();                    // B(i), A(i+1) published

        // ---- MMA phase on A(i&1), B ----
        const uint32_t abuf = sb + A_OFF + (uint32_t)(i & 1) * 32768;
        const uint32_t bhB = sb + BT_OFF, blB = sb + BT_OFF + 4096;
#pragma unroll
        for (int ks = 0; ks < 2; ks++) {
            // B fragments: rows k, units per x4.trans
            int rk = ks * 16 + (lid & 7) + ((lid >> 3 & 1) << 3);
            int uof = lid >> 4;
            uint32_t bh[8], bl[8];
#pragma unroll
            for (int q = 0; q < 2; q++) {
                uint32_t u = (uint32_t)(wn * 4 + 2 * q + uof);
                uint32_t ba = (uint32_t)rk * 128 + ((u ^ (uint32_t)(rk & 7)) * 16);
                LDSM4T(bh[q*4+0], bh[q*4+1], bh[q*4+2], bh[q*4+3], bhB + ba);
                LDSM4T(bl[q*4+0], bl[q*4+1], bl[q*4+2], bl[q*4+3], blB + ba);
            }
            const int uah = 2 * ks + half;       // A hi unit
            const int ual = uah | 4;             // A lo unit
#pragma unroll
            for (int mt = 0; mt < 4; mt++) {
                int rA = wm * 64 + mt * 16 + (lid & 15);
                uint32_t arow = abuf + (uint32_t)rA * 128;
                uint32_t ah0, ah1, ah2, ah3, al0, al1, al2, al3;
                LDSM4(ah0, ah1, ah2, ah3, arow + ((uint32_t)(uah ^ (rA & 7)) * 16));
                LDSM4(al0, al1, al2, al3, arow + ((uint32_t)(ual ^ (rA & 7)) * 16));
#pragma unroll
                for (int nt = 0; nt < 4; nt++) {
                    MMA16816(acc[mt][nt], ah0, ah1, ah2, ah3, bh[nt*2], bh[nt*2+1]);
                    MMA16816(acc[mt][nt], ah0, ah1, ah2, ah3, bl[nt*2], bl[nt*2+1]);
                    MMA16816(acc[mt][nt], al0, al1, al2, al3, bh[nt*2], bh[nt*2+1]);
                }
            }
        }
    }

    // ---- epilogue: direct float2 stores (n-pairs stay within a batch) ----
#pragma unroll
    for (int mt = 0; mt < 4; mt++) {
#pragma unroll
        for (int nt = 0; nt < 4; nt++) {
            int m = wm * 64 + mt * 16 + (lid >> 2);
            int n = n0 + wn * 32 + nt * 8 + ((lid & 3) << 1);
            int b2 = n / NPB, p2 = n - b2 * NPB;
            float* o = out + ((size_t)b2 * COUT + m) * NPB + p2;
            *(float2*)o = make_float2(acc[mt][nt][0], acc[mt][nt][1]);
            *(float2*)(o + 8 * NPB) = make_float2(acc[mt][nt][2], acc[mt][nt][3]);
        }
    }
}

// ============================================================================
extern "C" void kernel_launch(void* const* d_in, const int* in_sizes, int n_in,
                              void* d_out, int out_size) {
    const float* x  = (const float*)d_in[0];
    const float* gw = (const float*)d_in[1];
    const float* gb = (const float*)d_in[2];
    const float* gm = (const float*)d_in[3];
    const float* gv = (const float*)d_in[4];
    const float* cw = (const float*)d_in[5];
    float* out = (float*)d_out;

    cudaFuncSetAttribute(fused_all, cudaFuncAttributeMaxDynamicSharedMemorySize, SMEM_TOT);
    fused_all<<<NTOT / BN, 256, SMEM_TOT>>>(x, gw, gb, gm, gv, cw, out);
}

// round 5
// speedup vs baseline: 1.1099x; 1.1099x over previous
#include <cuda_runtime.h>
#include <cuda_bf16.h>
#include <cstdint>

// ---------------- problem constants ----------------
#define B_    16
#define CIN   512
#define COUT  256
#define H_    56
#define W_    56
#define HO    28
#define WO    28
#define NPB   784
#define NTOT  (B_ * NPB)      // 12544
#define HW    (H_ * W_)       // 3136
#define CH    32              // channels (k) per chunk
#define NCHK  (CIN / CH)      // 16
#define BN    32              // n per CTA tile
#define BM    256             // full M per CTA

// smem layout (bytes)
#define A_OFF 0               // 2 x 32KB : A [m][hi 64B | lo 64B], 128B rows, swizzled
#define B_OFF 65536           // 2 x 4KB  : B [k][hi 32n | lo 32n], 128B rows, swizzled
#define S_OFF 73728           // s_sc[512] + s_sh[512]
#define SMEM_TOT 77824

__device__ __forceinline__ uint32_t smem_u32(const void* p) {
    uint32_t a;
    asm("{ .reg .u64 t; cvta.to.shared.u64 t, %1; cvt.u32.u64 %0, t; }" : "=r"(a) : "l"(p));
    return a;
}
#define LDSM4(R0, R1, R2, R3, A) \
    asm volatile("ldmatrix.sync.aligned.m8n8.x4.shared.b16 {%0,%1,%2,%3}, [%4];" \
                 : "=r"(R0), "=r"(R1), "=r"(R2), "=r"(R3) : "r"(A))
#define LDSM4T(R0, R1, R2, R3, A) \
    asm volatile("ldmatrix.sync.aligned.m8n8.x4.trans.shared.b16 {%0,%1,%2,%3}, [%4];" \
                 : "=r"(R0), "=r"(R1), "=r"(R2), "=r"(R3) : "r"(A))
#define MMA16816(C, A0, A1, A2, A3, B0, B1) \
    asm volatile("mma.sync.aligned.m16n8k16.row.col.f32.bf16.bf16.f32 " \
                 "{%0,%1,%2,%3}, {%4,%5,%6,%7}, {%8,%9}, {%0,%1,%2,%3};" \
                 : "+f"((C)[0]), "+f"((C)[1]), "+f"((C)[2]), "+f"((C)[3]) \
                 : "r"(A0), "r"(A1), "r"(A2), "r"(A3), "r"(B0), "r"(B1))

// ============================================================================
// Fully fused: BN+ReLU+pool + W bf16 split + bf16x3 tensor-core GEMM
// 392 CTAs (BN=32), 256 thr, 2 CTAs/SM. Double-buffered A/B, 1 barrier/chunk.
// ============================================================================
__global__ __launch_bounds__(256, 2)
void fused_all(const float* __restrict__ x,
               const float* __restrict__ gamma,
               const float* __restrict__ beta,
               const float* __restrict__ mean,
               const float* __restrict__ var,
               const float* __restrict__ Wc,
               float* __restrict__ out) {
    extern __shared__ char sm[];
    const uint32_t sb = smem_u32(sm);
    const int tid = threadIdx.x;
    const int lid = tid & 31, wid = tid >> 5;
    const int n0 = blockIdx.x * BN;

    float* s_sc = (float*)(sm + S_OFF);
    float* s_sh = s_sc + 512;

    // ---- BN constants ----
    {
        int c = tid;
        float sc = gamma[c] * rsqrtf(var[c] + 1e-5f);
        s_sc[c] = sc;  s_sh[c] = beta[c] - mean[c] * sc;
        c += 256;
        sc = gamma[c] * rsqrtf(var[c] + 1e-5f);
        s_sc[c] = sc;  s_sh[c] = beta[c] - mean[c] * sc;
    }
    __syncthreads();

    // ---- pool role: thread owns n-pair pr, channel column cgq ----
    const int pr  = tid & 15;           // n-pair 0..15 (n = n0+2pr, +1)
    const int cgq = tid >> 4;           // 0..15
    const int nn = n0 + 2 * pr;
    const int bb = nn / NPB;
    const int pp = nn - bb * NPB;
    const int ho = pp / WO, wo = pp - ho * WO;          // wo even
    const float* xb = x + ((size_t)bb * CIN * H_ + 2 * ho) * W_ + 2 * wo;

    // ---- W-split role ----
    const int ufp = tid & 7;
    const int mr0 = tid >> 3;           // 0..31
    const float* wrow = Wc + (size_t)mr0 * CIN + ufp * 4;

    // ---- consumer role: warp tile 32m x 32n ----
    const int half = lid >> 4;          // A unit half / B uof

    float acc[2][4][4];
#pragma unroll
    for (int a = 0; a < 2; a++)
#pragma unroll
        for (int b = 0; b < 4; b++)
#pragma unroll
            for (int c = 0; c < 4; c++) acc[a][b][c] = 0.f;

    // ---- W chunk j -> A[j&1], fp32 -> bf16 hi/lo split, swizzled ----
    auto w_split = [&](int j) {
        const float* ws = wrow + j * CH;
        char* abase = sm + A_OFF + (size_t)(j & 1) * 32768;
#pragma unroll
        for (int g = 0; g < 8; g++) {
            float4 wv = *(const float4*)(ws + (size_t)g * 32 * CIN);
            int m = mr0 + 32 * g;
            __nv_bfloat16 h0 = __float2bfloat16(wv.x), h1 = __float2bfloat16(wv.y);
            __nv_bfloat16 h2 = __float2bfloat16(wv.z), h3 = __float2bfloat16(wv.w);
            __nv_bfloat16 l0 = __float2bfloat16(wv.x - __bfloat162float(h0));
            __nv_bfloat16 l1 = __float2bfloat16(wv.y - __bfloat162float(h1));
            __nv_bfloat16 l2 = __float2bfloat16(wv.z - __bfloat162float(h2));
            __nv_bfloat16 l3 = __float2bfloat16(wv.w - __bfloat162float(h3));
            uint2 hp, lp;
            hp.x = ((uint32_t)__bfloat16_as_ushort(h1) << 16) | __bfloat16_as_ushort(h0);
            hp.y = ((uint32_t)__bfloat16_as_ushort(h3) << 16) | __bfloat16_as_ushort(h2);
            lp.x = ((uint32_t)__bfloat16_as_ushort(l1) << 16) | __bfloat16_as_ushort(l0);
            lp.y = ((uint32_t)__bfloat16_as_ushort(l3) << 16) | __bfloat16_as_ushort(l2);
            uint32_t rowb = (uint32_t)m * 128 + (ufp & 1) * 8;
            *(uint2*)(abase + rowb + ((uint32_t)((ufp >> 1) ^ (m & 7)) * 16))       = hp;
            *(uint2*)(abase + rowb + ((uint32_t)(((ufp >> 1) | 4) ^ (m & 7)) * 16)) = lp;
        }
    };

    // ---- pool chunk i -> B[i&1]: BN+ReLU+avgpool + bf16 hi/lo split ----
    auto pool = [&](int i) {
        const int ch0 = i * CH;
        char* bbase = sm + B_OFF + (size_t)(i & 1) * 4096;
        const uint32_t sub = (uint32_t)(pr & 3) * 4;
        const uint32_t uhi = (uint32_t)(pr >> 2);
#pragma unroll
        for (int i2 = 0; i2 < 2; i2++) {
            int cl = cgq + 16 * i2;
            float sc = s_sc[ch0 + cl], sh = s_sh[ch0 + cl];
            const float* xp = xb + (size_t)(ch0 + cl) * HW;
            float4 r0 = *(const float4*)xp;
            float4 r1 = *(const float4*)(xp + W_);
            float v0 = fmaxf(fmaf(r0.x, sc, sh), 0.f) + fmaxf(fmaf(r0.y, sc, sh), 0.f)
                     + fmaxf(fmaf(r1.x, sc, sh), 0.f) + fmaxf(fmaf(r1.y, sc, sh), 0.f);
            float v1 = fmaxf(fmaf(r0.z, sc, sh), 0.f) + fmaxf(fmaf(r0.w, sc, sh), 0.f)
                     + fmaxf(fmaf(r1.z, sc, sh), 0.f) + fmaxf(fmaf(r1.w, sc, sh), 0.f);
            v0 *= 0.25f; v1 *= 0.25f;
            __nv_bfloat16 h0 = __float2bfloat16(v0), h1 = __float2bfloat16(v1);
            __nv_bfloat16 e0 = __float2bfloat16(v0 - __bfloat162float(h0));
            __nv_bfloat16 e1 = __float2bfloat16(v1 - __bfloat162float(h1));
            uint32_t hp = ((uint32_t)__bfloat16_as_ushort(h1) << 16) | __bfloat16_as_ushort(h0);
            uint32_t lp = ((uint32_t)__bfloat16_as_ushort(e1) << 16) | __bfloat16_as_ushort(e0);
            uint32_t rb = (uint32_t)cl * 128;
            *(uint32_t*)(bbase + rb + ((uhi       ^ (uint32_t)(cl & 7)) * 16) + sub) = hp;
            *(uint32_t*)(bbase + rb + (((uhi | 4) ^ (uint32_t)(cl & 7)) * 16) + sub) = lp;
        }
    };

    // ---- MMA on chunk i buffers ----
    auto mma = [&](int i) {
        const uint32_t abuf = sb + A_OFF + (uint32_t)(i & 1) * 32768;
        const uint32_t bbuf = sb + B_OFF + (uint32_t)(i & 1) * 4096;
#pragma unroll
        for (int ks = 0; ks < 2; ks++) {
            int rk = ks * 16 + (lid & 7) + (((lid >> 3) & 1) << 3);
            uint32_t brow = bbuf + (uint32_t)rk * 128;
            uint32_t bh[8], bl[8];
#pragma unroll
            for (int q = 0; q < 2; q++) {
                uint32_t u = (uint32_t)(2 * q + half);
                LDSM4T(bh[q*4+0], bh[q*4+1], bh[q*4+2], bh[q*4+3],
                       brow + ((u ^ (uint32_t)(rk & 7)) * 16));
                LDSM4T(bl[q*4+0], bl[q*4+1], bl[q*4+2], bl[q*4+3],
                       brow + (((u | 4) ^ (uint32_t)(rk & 7)) * 16));
            }
            const int uah = 2 * ks + half;
            const int ual = uah | 4;
#pragma unroll
            for (int mt = 0; mt < 2; mt++) {
                int rA = wid * 32 + mt * 16 + (lid & 15);
                uint32_t arow = abuf + (uint32_t)rA * 128;
                uint32_t ah0, ah1, ah2, ah3, al0, al1, al2, al3;
                LDSM4(ah0, ah1, ah2, ah3, arow + ((uint32_t)(uah ^ (rA & 7)) * 16));
                LDSM4(al0, al1, al2, al3, arow + ((uint32_t)(ual ^ (rA & 7)) * 16));
#pragma unroll
                for (int nt = 0; nt < 4; nt++) {
                    MMA16816(acc[mt][nt], ah0, ah1, ah2, ah3, bh[nt*2], bh[nt*2+1]);
                    MMA16816(acc[mt][nt], ah0, ah1, ah2, ah3, bl[nt*2], bl[nt*2+1]);
                    MMA16816(acc[mt][nt], al0, al1, al2, al3, bh[nt*2], bh[nt*2+1]);
                }
            }
        }
    };

    // ---- prologue ----
    w_split(0);
    pool(0);
    __syncthreads();

    // ---- main loop: 1 barrier per chunk, producers target opposite buffer ----
    for (int i = 0; i < NCHK; i++) {
        mma(i);
        if (i + 1 < NCHK) {
            w_split(i + 1);
            pool(i + 1);
            __syncthreads();
        }
    }

    // ---- epilogue: direct float2 stores (c2,c3 are m+8 rows) ----
#pragma unroll
    for (int mt = 0; mt < 2; mt++) {
#pragma unroll
        for (int nt = 0; nt < 4; nt++) {
            int m = wid * 32 + mt * 16 + (lid >> 2);
            int n = n0 + nt * 8 + ((lid & 3) << 1);
            int b2 = n / NPB, p2 = n - b2 * NPB;
            float* o = out + ((size_t)b2 * COUT + m) * NPB + p2;
            *(float2*)o = make_float2(acc[mt][nt][0], acc[mt][nt][1]);
            *(float2*)(o + 8 * NPB) = make_float2(acc[mt][nt][2], acc[mt][nt][3]);
        }
    }
}

// ============================================================================
extern "C" void kernel_launch(void* const* d_in, const int* in_sizes, int n_in,
                              void* d_out, int out_size) {
    const float* x  = (const float*)d_in[0];
    const float* gw = (const float*)d_in[1];
    const float* gb = (const float*)d_in[2];
    const float* gm = (const float*)d_in[3];
    const float* gv = (const float*)d_in[4];
    const float* cw = (const float*)d_in[5];
    float* out = (float*)d_out;

    cudaFuncSetAttribute(fused_all, cudaFuncAttributeMaxDynamicSharedMemorySize, SMEM_TOT);
    fused_all<<<NTOT / BN, 256, SMEM_TOT>>>(x, gw, gb, gm, gv, cw, out);
}